// round 14
// baseline (speedup 1.0000x reference)
#include <cuda_runtime.h>
#include <cuda_bf16.h>
#include <cuda_fp16.h>
#include <math.h>
#include <stdint.h>

#define BB   8
#define SS   1024
#define DD   1024
#define HH   16
#define DK   64

__device__ __forceinline__ uint32_t smem_u32(const void* p) {
    uint32_t a;
    asm("{ .reg .u64 t; cvta.to.shared.u64 t, %1; cvt.u32.u64 %0, t; }"
        : "=r"(a) : "l"(p));
    return a;
}

#define CP_ASYNC16(dst, src) \
    asm volatile("cp.async.cg.shared.global [%0], [%1], 16;" :: "r"(dst), "l"(src))
#define CP_COMMIT() asm volatile("cp.async.commit_group;" ::: "memory")
#define CP_WAIT0()  asm volatile("cp.async.wait_group 0;" ::: "memory")
#define CP_WAIT1()  asm volatile("cp.async.wait_group 1;" ::: "memory")

#define LDSM4(r, a)                                                          \
    asm volatile("ldmatrix.sync.aligned.m8n8.x4.shared.b16 {%0,%1,%2,%3}, [%4];" \
        : "=r"((r)[0]), "=r"((r)[1]), "=r"((r)[2]), "=r"((r)[3]) : "r"(a))
#define LDSM4T(r, a)                                                         \
    asm volatile("ldmatrix.sync.aligned.m8n8.x4.trans.shared.b16 {%0,%1,%2,%3}, [%4];" \
        : "=r"((r)[0]), "=r"((r)[1]), "=r"((r)[2]), "=r"((r)[3]) : "r"(a))

#define MMA_BF16(c, a, b)                                                    \
    asm volatile("mma.sync.aligned.m16n8k16.row.col.f32.bf16.bf16.f32 "      \
        "{%0,%1,%2,%3}, {%4,%5,%6,%7}, {%8,%9}, {%0,%1,%2,%3};"              \
        : "+f"((c)[0]), "+f"((c)[1]), "+f"((c)[2]), "+f"((c)[3])             \
        : "r"((a)[0]), "r"((a)[1]), "r"((a)[2]), "r"((a)[3]),                \
          "r"((b)[0]), "r"((b)[1]))
#define MMA_F16(c, a, b)                                                     \
    asm volatile("mma.sync.aligned.m16n8k16.row.col.f32.f16.f16.f32 "        \
        "{%0,%1,%2,%3}, {%4,%5,%6,%7}, {%8,%9}, {%0,%1,%2,%3};"              \
        : "+f"((c)[0]), "+f"((c)[1]), "+f"((c)[2]), "+f"((c)[3])             \
        : "r"((a)[0]), "r"((a)[1]), "r"((a)[2]), "r"((a)[3]),                \
          "r"((b)[0]), "r"((b)[1]))

__device__ __forceinline__ uint32_t packh2(float a, float b) {
    __half2 h = __floats2half2_rn(a, b);
    return *(uint32_t*)&h;
}
__device__ __forceinline__ uint32_t packbf2(float a, float b) {
    __nv_bfloat16 x = __float2bfloat16(a), y = __float2bfloat16(b);
    return (uint32_t)*(unsigned short*)&x | ((uint32_t)*(unsigned short*)&y << 16);
}

// ---------------------------------------------------------------------------
// Global scratch
// ---------------------------------------------------------------------------
__device__ float g_bias[HH * (2 * SS - 1)];
__device__ __nv_bfloat16 g_ahi[BB * SS * DD];
__device__ __nv_bfloat16 g_alo[BB * SS * DD];
__device__ __half        g_x16[BB * SS * DD];
__device__ __half        g_ctx16[BB * SS * DD];
__device__ __nv_bfloat16 g_wthi[2 * DD * DD];
__device__ __nv_bfloat16 g_wtlo[2 * DD * DD];
__device__ __half        g_w16[2 * DD * DD];
__device__ __nv_bfloat16 g_qhi[BB * HH * SS * DK];
__device__ __nv_bfloat16 g_qlo[BB * HH * SS * DK];
__device__ __nv_bfloat16 g_khi[BB * HH * SS * DK];
__device__ __nv_bfloat16 g_klo[BB * HH * SS * DK];
__device__ __half        g_vh [BB * HH * SS * DK];

// ---------------------------------------------------------------------------
// Bias table
// ---------------------------------------------------------------------------
__global__ void bias_kernel(const float* __restrict__ rel_emb) {
    int idx = blockIdx.x * blockDim.x + threadIdx.x;
    const int TAB = 2 * SS - 1;
    if (idx >= HH * TAB) return;
    int h = idx / TAB, pos = idx % TAB;
    int n = -(pos - (SS - 1));
    int ret = 0;
    if (n < 0) { ret = 16; n = -n; }
    int v;
    if (n < 8) v = n;
    else {
        int j = (31 - __clz(n * n)) - 6;
        v = 8 + j;
        if (v > 15) v = 15;
    }
    g_bias[idx] = rel_emb[(ret + v) * HH + h];
}

// ---------------------------------------------------------------------------
// fp32 -> bf16 hi/lo + fp16 (x)
// ---------------------------------------------------------------------------
__global__ void split_kernel(const float* __restrict__ src,
                             __nv_bfloat16* __restrict__ hi,
                             __nv_bfloat16* __restrict__ lo,
                             __half* __restrict__ h16, int n4) {
    int i = blockIdx.x * blockDim.x + threadIdx.x;
    if (i >= n4) return;
    float4 v = ((const float4*)src)[i];
    __nv_bfloat16 h[4], l[4];
    __half f[4];
    float vv[4] = {v.x, v.y, v.z, v.w};
#pragma unroll
    for (int j = 0; j < 4; ++j) {
        h[j] = __float2bfloat16(vv[j]);
        l[j] = __float2bfloat16(vv[j] - __bfloat162float(h[j]));
        f[j] = __float2half_rn(vv[j]);
    }
    *(uint2*)&hi[4 * i] = *(uint2*)h;
    *(uint2*)&lo[4 * i] = *(uint2*)l;
    *(uint2*)&h16[4 * i] = *(uint2*)f;
}

// ---------------------------------------------------------------------------
// Fused transpose+split of all 4 weights
// ---------------------------------------------------------------------------
__global__ void splitT4_kernel(const float* __restrict__ W0,
                               const float* __restrict__ W1,
                               const float* __restrict__ W2,
                               const float* __restrict__ W3,
                               __nv_bfloat16* __restrict__ hi,
                               __nv_bfloat16* __restrict__ lo,
                               __half* __restrict__ w16) {
    __shared__ float t[32][33];
    const int tx = threadIdx.x, ty = threadIdx.y;
    const int bx = blockIdx.x, by = blockIdx.y, bz = blockIdx.z;
    const float* W = (bz == 0) ? W0 : (bz == 1) ? W1 : (bz == 2) ? W2 : W3;
#pragma unroll
    for (int j = 0; j < 32; j += 8)
        t[ty + j][tx] = W[(by * 32 + ty + j) * DD + bx * 32 + tx];
    __syncthreads();
#pragma unroll
    for (int j = 0; j < 32; j += 8) {
        float v = t[tx][ty + j];
        size_t row = (size_t)(bx * 32 + ty + j) * DD + by * 32 + tx;
        if (bz < 2) {
            size_t o = (size_t)bz * DD * DD + row;
            __nv_bfloat16 h = __float2bfloat16(v);
            hi[o] = h;
            lo[o] = __float2bfloat16(v - __bfloat162float(h));
        } else {
            w16[(size_t)(bz - 2) * DD * DD + row] = __float2half_rn(v);
        }
    }
}

// ---------------------------------------------------------------------------
// Fused Q+K GEMM (N=2048), bf16 3-product split.
// Mainloop reordered: half-B-granularity ldsm/MMA interleave (same regs).
// ---------------------------------------------------------------------------
#define T_B    8192
#define STG_B  (4 * T_B)
#define GEMM_SMEM (3 * STG_B)

__global__ __launch_bounds__(256, 2)
void tc_gemm_qk(const __nv_bfloat16* __restrict__ Ahi,
                const __nv_bfloat16* __restrict__ Alo,
                const __nv_bfloat16* __restrict__ Bhi,
                const __nv_bfloat16* __restrict__ Blo,
                void* __restrict__ oQh, void* __restrict__ oQl,
                void* __restrict__ oKh, void* __restrict__ oKl) {
    extern __shared__ __align__(128) char smc[];
    const uint32_t sb = smem_u32(smc);
    const int tid = threadIdx.x;
    const int lane = tid & 31, wid = tid >> 5;
    const int m0 = blockIdx.y * 128, n0 = blockIdx.x * 128;

    const int wm = (wid & 3) * 32;
    const int wn = (wid >> 2) * 64;

    const int arow = wm + (lane & 15);
    const uint32_t abase = (uint32_t)arow * 64;
    const int aswz = (arow >> 1) & 3;
    const int ahb = lane >> 4;
    const int brow = wn + (lane & 7) + (lane >> 4) * 8;
    const uint32_t bbase = (uint32_t)brow * 64;
    const int bswz = (brow >> 1) & 3;
    const int bhb = (lane >> 3) & 1;

    float c[2][8][4];
#pragma unroll
    for (int i = 0; i < 2; ++i)
#pragma unroll
        for (int j = 0; j < 8; ++j)
#pragma unroll
            for (int q = 0; q < 4; ++q) c[i][j][q] = 0.0f;

    const int NIT = 32;

    auto issue = [&](int t) {
        const int kb = t * 32;
        const uint32_t stg = sb + (t % 3) * STG_B;
        const char* s0 = (const char*)(Ahi + (size_t)m0 * DD + kb);
        const char* s1 = (const char*)(Alo + (size_t)m0 * DD + kb);
        const char* s2 = (const char*)(Bhi + (size_t)n0 * DD + kb);
        const char* s3 = (const char*)(Blo + (size_t)n0 * DD + kb);
#pragma unroll
        for (int j = 0; j < 8; ++j) {
            const int idx = tid + j * 256;
            const int tile = idx >> 9, rem = idx & 511;
            const int row = rem >> 2, ch = rem & 3;
            const int phys = ch ^ ((row >> 1) & 3);
            const char* src =
                ((tile == 0) ? s0 : (tile == 1) ? s1 : (tile == 2) ? s2 : s3) +
                (size_t)row * 2048 + ch * 16;
            CP_ASYNC16(stg + tile * T_B + row * 64 + phys * 16, src);
        }
    };

    issue(0); CP_COMMIT();
    issue(1); CP_COMMIT();

    for (int t = 0; t < NIT; ++t) {
        CP_WAIT1();
        __syncthreads();
        if (t + 2 < NIT) issue(t + 2);
        CP_COMMIT();

        const uint32_t stg = sb + (t % 3) * STG_B;
#pragma unroll
        for (int s = 0; s < 2; ++s) {
            const uint32_t ac = (uint32_t)(((s * 2 + ahb) ^ aswz) * 16);
            const uint32_t bc = (uint32_t)(((s * 2 + bhb) ^ bswz) * 16);
            uint32_t ah[2][4], al[2][4], bf[4][4];
            // A frags + first half of Bhi
#pragma unroll
            for (int mi = 0; mi < 2; ++mi) {
                LDSM4(ah[mi], stg + abase + mi * 1024 + ac);
                LDSM4(al[mi], stg + T_B + abase + mi * 1024 + ac);
            }
            LDSM4(bf[0], stg + 2 * T_B + bbase + 0 * 1024 + bc);
            LDSM4(bf[1], stg + 2 * T_B + bbase + 1 * 1024 + bc);
            // second half of Bhi issues ahead of its consumers
            LDSM4(bf[2], stg + 2 * T_B + bbase + 2 * 1024 + bc);
            LDSM4(bf[3], stg + 2 * T_B + bbase + 3 * 1024 + bc);
            // hh + lh on nj 0..3 (reads bf[0..1])
#pragma unroll
            for (int mi = 0; mi < 2; ++mi)
#pragma unroll
                for (int nj = 0; nj < 4; ++nj) {
                    uint32_t b2[2] = {bf[nj >> 1][(nj & 1) * 2],
                                      bf[nj >> 1][(nj & 1) * 2 + 1]};
                    MMA_BF16(c[mi][nj], ah[mi], b2);
                    MMA_BF16(c[mi][nj], al[mi], b2);
                }
            // Blo first half (overwrites bf[0..1], WAR-safe after issue)
            LDSM4(bf[0], stg + 3 * T_B + bbase + 0 * 1024 + bc);
            LDSM4(bf[1], stg + 3 * T_B + bbase + 1 * 1024 + bc);
            // hh + lh on nj 4..7 (reads bf[2..3])
#pragma unroll
            for (int mi = 0; mi < 2; ++mi)
#pragma unroll
                for (int nj = 4; nj < 8; ++nj) {
                    uint32_t b2[2] = {bf[nj >> 1][(nj & 1) * 2],
                                      bf[nj >> 1][(nj & 1) * 2 + 1]};
                    MMA_BF16(c[mi][nj], ah[mi], b2);
                    MMA_BF16(c[mi][nj], al[mi], b2);
                }
            // Blo second half
            LDSM4(bf[2], stg + 3 * T_B + bbase + 2 * 1024 + bc);
            LDSM4(bf[3], stg + 3 * T_B + bbase + 3 * 1024 + bc);
            // hl on nj 0..3 (bf[0..1] now Blo)
#pragma unroll
            for (int mi = 0; mi < 2; ++mi)
#pragma unroll
                for (int nj = 0; nj < 4; ++nj) {
                    uint32_t b2[2] = {bf[nj >> 1][(nj & 1) * 2],
                                      bf[nj >> 1][(nj & 1) * 2 + 1]};
                    MMA_BF16(c[mi][nj], ah[mi], b2);
                }
            // hl on nj 4..7
#pragma unroll
            for (int mi = 0; mi < 2; ++mi)
#pragma unroll
                for (int nj = 4; nj < 8; ++nj) {
                    uint32_t b2[2] = {bf[nj >> 1][(nj & 1) * 2],
                                      bf[nj >> 1][(nj & 1) * 2 + 1]};
                    MMA_BF16(c[mi][nj], ah[mi], b2);
                }
        }
    }

    const int sect = n0 >> 10;
    void* oh = (sect == 0) ? oQh : oKh;
    void* ol = (sect == 0) ? oQl : oKl;
#pragma unroll
    for (int mi = 0; mi < 2; ++mi) {
#pragma unroll
        for (int nj = 0; nj < 8; ++nj) {
            const int col = n0 + wn + nj * 8 + (lane & 3) * 2;
            const int r = m0 + wm + mi * 16 + (lane >> 2);
            const int cw = col & 1023;
            const int h = cw >> 6, d = cw & 63;
#pragma unroll
            for (int half = 0; half < 2; ++half) {
                const int rr = r + half * 8;
                const int b = rr >> 10, s2 = rr & 1023;
                const size_t idx = ((size_t)((b << 4) + h) * 1024 + s2) * 64 + d;
                float v0 = c[mi][nj][half * 2], v1 = c[mi][nj][half * 2 + 1];
                __nv_bfloat16 h0 = __float2bfloat16(v0);
                __nv_bfloat16 h1 = __float2bfloat16(v1);
                ((uint32_t*)oh)[idx >> 1] =
                    (uint32_t)*(unsigned short*)&h0 |
                    ((uint32_t)*(unsigned short*)&h1 << 16);
                ((uint32_t*)ol)[idx >> 1] = packbf2(
                    v0 - __bfloat162float(h0), v1 - __bfloat162float(h1));
            }
        }
    }
}

// ---------------------------------------------------------------------------
// fp16 single-product GEMM, k64 stages + phase-level frag double buffering
// (R13 version — faster in isolation).
//   MODE 0: fp32 row-major out (Wo).  MODE 1: fp16 scatter [B,H,S,DK] (V).
// ---------------------------------------------------------------------------
#define T16_B  16384
#define STG16  (2 * T16_B)
#define GEMM16_SMEM (3 * STG16)

template <int MODE>
__global__ __launch_bounds__(256, 2)
void tc_gemm16(const __half* __restrict__ A,
               const __half* __restrict__ Bm,
               void* __restrict__ out) {
    extern __shared__ __align__(128) char smc[];
    const uint32_t sb = smem_u32(smc);
    const int tid = threadIdx.x;
    const int lane = tid & 31, wid = tid >> 5;
    const int m0 = blockIdx.y * 128, n0 = blockIdx.x * 128;

    const int wm = (wid & 3) * 32;
    const int wn = (wid >> 2) * 64;
    const int arow = wm + (lane & 15);
    const uint32_t abase = (uint32_t)arow * 128;
    const int asw = arow & 7;
    const int ahb = lane >> 4;
    const int brow = wn + (lane & 7) + (lane >> 4) * 8;
    const uint32_t bbase = (uint32_t)brow * 128;
    const int bsw = brow & 7;
    const int bhb = (lane >> 3) & 1;

    float c[2][8][4];
#pragma unroll
    for (int i = 0; i < 2; ++i)
#pragma unroll
        for (int j = 0; j < 8; ++j)
#pragma unroll
            for (int q = 0; q < 4; ++q) c[i][j][q] = 0.0f;

    const int NIT = 16;

    auto issue = [&](int t) {
        const int kbB = t * 128;
        const uint32_t stg = sb + (t % 3) * STG16;
        const char* s0 = (const char*)(A + (size_t)m0 * DD) + kbB;
        const char* s1 = (const char*)(Bm + (size_t)n0 * DD) + kbB;
#pragma unroll
        for (int j = 0; j < 8; ++j) {
            const int idx = tid + j * 256;
            const int tile = idx >> 10, rem = idx & 1023;
            const int row = rem >> 3, ch = rem & 7;
            const int phys = ch ^ (row & 7);
            const char* src = (tile ? s1 : s0) + (size_t)row * 2048 + ch * 16;
            CP_ASYNC16(stg + tile * T16_B + row * 128 + phys * 16, src);
        }
    };

    issue(0); CP_COMMIT();
    issue(1); CP_COMMIT();

    for (int t = 0; t < NIT; ++t) {
        CP_WAIT1();
        __syncthreads();
        if (t + 2 < NIT) issue(t + 2);
        CP_COMMIT();

        const uint32_t stg = sb + (t % 3) * STG16;
        uint32_t ah[2][2][4], bf[2][4][4];
        {
            const uint32_t ac0 = (uint32_t)((ahb ^ asw) * 16);
            const uint32_t bc0 = (uint32_t)((bhb ^ bsw) * 16);
#pragma unroll
            for (int mi = 0; mi < 2; ++mi)
                LDSM4(ah[0][mi], stg + abase + mi * (16 * 128) + ac0);
#pragma unroll
            for (int p = 0; p < 4; ++p)
                LDSM4(bf[0][p], stg + T16_B + bbase + p * (16 * 128) + bc0);
        }
#pragma unroll
        for (int s = 0; s < 4; ++s) {
            const int cur = s & 1;
            if (s < 3) {
                const uint32_t acn =
                    (uint32_t)((((s + 1) * 2 + ahb) ^ asw) * 16);
                const uint32_t bcn =
                    (uint32_t)((((s + 1) * 2 + bhb) ^ bsw) * 16);
#pragma unroll
                for (int mi = 0; mi < 2; ++mi)
                    LDSM4(ah[cur ^ 1][mi],
                          stg + abase + mi * (16 * 128) + acn);
#pragma unroll
                for (int p = 0; p < 4; ++p)
                    LDSM4(bf[cur ^ 1][p],
                          stg + T16_B + bbase + p * (16 * 128) + bcn);
            }
#pragma unroll
            for (int mi = 0; mi < 2; ++mi)
#pragma unroll
                for (int nj = 0; nj < 8; ++nj) {
                    uint32_t b2[2] = {bf[cur][nj >> 1][(nj & 1) * 2],
                                      bf[cur][nj >> 1][(nj & 1) * 2 + 1]};
                    MMA_F16(c[mi][nj], ah[cur][mi], b2);
                }
        }
    }

#pragma unroll
    for (int mi = 0; mi < 2; ++mi) {
#pragma unroll
        for (int nj = 0; nj < 8; ++nj) {
            const int col = n0 + wn + nj * 8 + (lane & 3) * 2;
            const int r = m0 + wm + mi * 16 + (lane >> 2);
            if (MODE == 0) {
                float* o = (float*)out;
                *(float2*)&o[(size_t)r * DD + col] =
                    make_float2(c[mi][nj][0], c[mi][nj][1]);
                *(float2*)&o[(size_t)(r + 8) * DD + col] =
                    make_float2(c[mi][nj][2], c[mi][nj][3]);
            } else {
                const int h = col >> 6, d = col & 63;
#pragma unroll
                for (int half = 0; half < 2; ++half) {
                    const int rr = r + half * 8;
                    const int b = rr >> 10, s2 = rr & 1023;
                    const size_t idx =
                        ((size_t)((b << 4) + h) * 1024 + s2) * 64 + d;
                    ((uint32_t*)out)[idx >> 1] =
                        packh2(c[mi][nj][half * 2], c[mi][nj][half * 2 + 1]);
                }
            }
        }
    }
}

// ---------------------------------------------------------------------------
// Tensor-core flash attention — UNCHANGED (proven).
// ---------------------------------------------------------------------------
#define KT      64
#define RSB     144
#define Q_B     (128 * RSB)
#define KV_T    (KT * RSB)
#define KV_STG  (3 * KV_T)
#define SM_KV   (2 * Q_B)
#define SM_BIAS (SM_KV + 2 * KV_STG)
#define ATT_SMEM (SM_BIAS + 1152 * 4)

__global__ __launch_bounds__(256, 2)
void attn_kernel() {
    extern __shared__ __align__(128) char smc[];
    const uint32_t sb = smem_u32(smc);
    float* bs = (float*)(smc + SM_BIAS);

    const int tid = threadIdx.x;
    const int lane = tid & 31, wid = tid >> 5;
    const int q0 = blockIdx.x * 128;
    const int h = blockIdx.y, b = blockIdx.z;
    const size_t hd = (size_t)(b * HH + h) * SS * DK;

    const int wm = wid * 16;
    const uint32_t aoff = (uint32_t)(wm + (lane & 15)) * RSB + (lane >> 4) * 16;
    const uint32_t boff = (uint32_t)((lane & 7) + (lane >> 4) * 8) * RSB +
                          ((lane >> 3) & 1) * 16;
    const uint32_t voff = (uint32_t)(lane & 15) * RSB + (lane >> 4) * 16;

    {
        const char* qh = (const char*)(g_qhi + hd + (size_t)q0 * DK);
        const char* ql = (const char*)(g_qlo + hd + (size_t)q0 * DK);
#pragma unroll
        for (int j = 0; j < 4; ++j) {
            int idx = tid + j * 256;
            int row = idx >> 3, ch = (idx & 7) * 16;
            CP_ASYNC16(sb + row * RSB + ch, qh + row * 128 + ch);
            CP_ASYNC16(sb + Q_B + row * RSB + ch, ql + row * 128 + ch);
        }
        for (int i = tid; i < 1151; i += 256)
            bs[i] = g_bias[h * (2 * SS - 1) + (896 - q0) + i];
    }
    auto issue_kv = [&](int kt) {
        const uint32_t stg = sb + SM_KV + (kt & 1) * KV_STG;
        const int k0 = kt * KT;
        const char* kh = (const char*)(g_khi + hd + (size_t)k0 * DK);
        const char* kl = (const char*)(g_klo + hd + (size_t)k0 * DK);
        const char* vv = (const char*)(g_vh + hd + (size_t)k0 * DK);
#pragma unroll
        for (int j = 0; j < 6; ++j) {
            int idx = tid + j * 256;
            int tile = idx >> 9, rem = idx & 511;
            int row = rem >> 3, ch = (rem & 7) * 16;
            const char* src = (tile == 0 ? kh : (tile == 1 ? kl : vv));
            CP_ASYNC16(stg + tile * KV_T + row * RSB + ch, src + row * 128 + ch);
        }
    };
    issue_kv(0);
    CP_COMMIT();

    float o[8][4];
#pragma unroll
    for (int j = 0; j < 8; ++j)
#pragma unroll
        for (int e = 0; e < 4; ++e) o[j][e] = 0.0f;
    float m0r = -1e30f, m1r = -1e30f, l0 = 0.0f, l1 = 0.0f;

    for (int kt = 0; kt < SS / KT; ++kt) {
        CP_WAIT0();
        __syncthreads();
        if (kt + 1 < SS / KT) { issue_kv(kt + 1); CP_COMMIT(); }

        const uint32_t kbh = sb + SM_KV + (kt & 1) * KV_STG;
        const uint32_t kbl = kbh + KV_T;
        const uint32_t vbb = kbh + 2 * KV_T;
        const int k0 = kt * KT;

        float s[8][4];
#pragma unroll
        for (int j = 0; j < 8; ++j)
#pragma unroll
            for (int e = 0; e < 4; ++e) s[j][e] = 0.0f;

#pragma unroll
        for (int ks = 0; ks < 4; ++ks) {
            uint32_t ah[4], al[4];
            LDSM4(ah, sb + aoff + ks * 32);
            LDSM4(al, sb + Q_B + aoff + ks * 32);
#pragma unroll
            for (int p = 0; p < 4; ++p) {
                uint32_t bh[4], bl[4];
                LDSM4(bh, kbh + boff + p * (16 * RSB) + ks * 32);
                LDSM4(bl, kbl + boff + p * (16 * RSB) + ks * 32);
                MMA_BF16(s[2 * p], ah, bh);
                MMA_BF16(s[2 * p + 1], ah, bh + 2);
                MMA_BF16(s[2 * p], al, bh);
                MMA_BF16(s[2 * p + 1], al, bh + 2);
                MMA_BF16(s[2 * p], ah, bl);
                MMA_BF16(s[2 * p + 1], ah, bl + 2);
            }
        }

        const int qr0 = wm + (lane >> 2);
        const int cb0 = 127 + k0 + (lane & 3) * 2;
#pragma unroll
        for (int nj = 0; nj < 8; ++nj) {
            const int t0 = cb0 + nj * 8;
            s[nj][0] += bs[t0 - qr0];
            s[nj][1] += bs[t0 + 1 - qr0];
            s[nj][2] += bs[t0 - qr0 - 8];
            s[nj][3] += bs[t0 + 1 - qr0 - 8];
        }
        float mx0 = -1e30f, mx1 = -1e30f;
#pragma unroll
        for (int nj = 0; nj < 8; ++nj) {
            mx0 = fmaxf(mx0, fmaxf(s[nj][0], s[nj][1]));
            mx1 = fmaxf(mx1, fmaxf(s[nj][2], s[nj][3]));
        }
        mx0 = fmaxf(mx0, __shfl_xor_sync(0xffffffffu, mx0, 1));
        mx0 = fmaxf(mx0, __shfl_xor_sync(0xffffffffu, mx0, 2));
        mx1 = fmaxf(mx1, __shfl_xor_sync(0xffffffffu, mx1, 1));
        mx1 = fmaxf(mx1, __shfl_xor_sync(0xffffffffu, mx1, 2));
        const float mn0 = fmaxf(m0r, mx0), mn1 = fmaxf(m1r, mx1);
        const float al0 = __expf(m0r - mn0), al1 = __expf(m1r - mn1);
        m0r = mn0; m1r = mn1;
        float sum0 = 0.0f, sum1 = 0.0f;
#pragma unroll
        for (int nj = 0; nj < 8; ++nj) {
            s[nj][0] = __expf(s[nj][0] - mn0);
            s[nj][1] = __expf(s[nj][1] - mn0);
            s[nj][2] = __expf(s[nj][2] - mn1);
            s[nj][3] = __expf(s[nj][3] - mn1);
            sum0 += s[nj][0] + s[nj][1];
            sum1 += s[nj][2] + s[nj][3];
            o[nj][0] *= al0; o[nj][1] *= al0;
            o[nj][2] *= al1; o[nj][3] *= al1;
        }
        sum0 += __shfl_xor_sync(0xffffffffu, sum0, 1);
        sum0 += __shfl_xor_sync(0xffffffffu, sum0, 2);
        sum1 += __shfl_xor_sync(0xffffffffu, sum1, 1);
        sum1 += __shfl_xor_sync(0xffffffffu, sum1, 2);
        l0 = l0 * al0 + sum0;
        l1 = l1 * al1 + sum1;

#pragma unroll
        for (int kc = 0; kc < 4; ++kc) {
            uint32_t ap[4];
            ap[0] = packh2(s[2 * kc][0], s[2 * kc][1]);
            ap[1] = packh2(s[2 * kc][2], s[2 * kc][3]);
            ap[2] = packh2(s[2 * kc + 1][0], s[2 * kc + 1][1]);
            ap[3] = packh2(s[2 * kc + 1][2], s[2 * kc + 1][3]);
#pragma unroll
            for (int nb = 0; nb < 4; ++nb) {
                uint32_t bt[4];
                LDSM4T(bt, vbb + voff + kc * (16 * RSB) + nb * 32);
                MMA_F16(o[2 * nb], ap, bt);
                MMA_F16(o[2 * nb + 1], ap, bt + 2);
            }
        }
    }

    const float inv0 = 1.0f / l0, inv1 = 1.0f / l1;
    const int row0 = q0 + wm + (lane >> 2);
    const size_t base0 = ((size_t)(b * SS) + row0) * DD + h * 64;
    const size_t base1 = base0 + 8 * DD;
#pragma unroll
    for (int nj = 0; nj < 8; ++nj) {
        const int d = nj * 8 + (lane & 3) * 2;
        ((uint32_t*)g_ctx16)[(base0 + d) >> 1] =
            packh2(o[nj][0] * inv0, o[nj][1] * inv0);
        ((uint32_t*)g_ctx16)[(base1 + d) >> 1] =
            packh2(o[nj][2] * inv1, o[nj][3] * inv1);
    }
}

// ---------------------------------------------------------------------------
// Launch — R11 topology (proven best).
// ---------------------------------------------------------------------------
extern "C" void kernel_launch(void* const* d_in, const int* in_sizes, int n_in,
                              void* d_out, int out_size) {
    const float* x   = (const float*)d_in[0];
    const float* Wq  = (const float*)d_in[1];
    const float* Wk  = (const float*)d_in[2];
    const float* Wv  = (const float*)d_in[3];
    const float* Wo  = (const float*)d_in[4];
    const float* rel = (const float*)d_in[5];
    float* out = (float*)d_out;

    __nv_bfloat16 *pah, *pal, *pwh, *pwl, *pqh, *pql, *pkh, *pkl;
    __half *pvh, *px16, *pc16, *pw16;
    cudaGetSymbolAddress((void**)&pah, g_ahi);
    cudaGetSymbolAddress((void**)&pal, g_alo);
    cudaGetSymbolAddress((void**)&px16, g_x16);
    cudaGetSymbolAddress((void**)&pc16, g_ctx16);
    cudaGetSymbolAddress((void**)&pwh, g_wthi);
    cudaGetSymbolAddress((void**)&pwl, g_wtlo);
    cudaGetSymbolAddress((void**)&pw16, g_w16);
    cudaGetSymbolAddress((void**)&pqh, g_qhi);
    cudaGetSymbolAddress((void**)&pql, g_qlo);
    cudaGetSymbolAddress((void**)&pkh, g_khi);
    cudaGetSymbolAddress((void**)&pkl, g_klo);
    cudaGetSymbolAddress((void**)&pvh, g_vh);

    static cudaStream_t sv = nullptr;
    static cudaEvent_t ev0 = nullptr, ev1 = nullptr, ev2 = nullptr, ev3 = nullptr;
    if (!sv) {
        cudaStreamCreateWithFlags(&sv, cudaStreamNonBlocking);
        cudaEventCreateWithFlags(&ev0, cudaEventDisableTiming);
        cudaEventCreateWithFlags(&ev1, cudaEventDisableTiming);
        cudaEventCreateWithFlags(&ev2, cudaEventDisableTiming);
        cudaEventCreateWithFlags(&ev3, cudaEventDisableTiming);
        cudaFuncSetAttribute(tc_gemm_qk, cudaFuncAttributeMaxDynamicSharedMemorySize, GEMM_SMEM);
        cudaFuncSetAttribute(tc_gemm16<0>, cudaFuncAttributeMaxDynamicSharedMemorySize, GEMM16_SMEM);
        cudaFuncSetAttribute(tc_gemm16<1>, cudaFuncAttributeMaxDynamicSharedMemorySize, GEMM16_SMEM);
        cudaFuncSetAttribute(attn_kernel, cudaFuncAttributeMaxDynamicSharedMemorySize, ATT_SMEM);
    }

    // fork: side stream does weights transpose/split + bias table
    cudaEventRecord(ev0, 0);
    cudaStreamWaitEvent(sv, ev0, 0);

    dim3 tg(32, 32, 4), tb(32, 8);
    splitT4_kernel<<<tg, tb, 0, sv>>>(Wq, Wk, Wv, Wo, pwh, pwl, pw16);
    bias_kernel<<<(HH * (2 * SS - 1) + 255) / 256, 256, 0, sv>>>(rel);

    const int n4 = BB * SS * DD / 4;
    split_kernel<<<(n4 + 255) / 256, 256>>>(x, pah, pal, px16, n4);

    // join: both split products ready
    cudaEventRecord(ev1, sv);
    cudaStreamWaitEvent(0, ev1, 0);

    // fork: V projection (side) concurrent with Q+K GEMM (main)
    cudaEventRecord(ev2, 0);
    cudaStreamWaitEvent(sv, ev2, 0);

    dim3 gv(DD / 128, (BB * SS) / 128);       // (8, 64)
    tc_gemm16<1><<<gv, 256, GEMM16_SMEM, sv>>>(px16, pw16, pvh);

    dim3 gqk(2 * DD / 128, (BB * SS) / 128);  // (16, 64)
    tc_gemm_qk<<<gqk, 256, GEMM_SMEM>>>(pah, pal, pwh, pwl,
                                        pqh, pql, pkh, pkl);

    // join before attention
    cudaEventRecord(ev3, sv);
    cudaStreamWaitEvent(0, ev3, 0);

    dim3 ag(SS / 128, HH, BB);
    attn_kernel<<<ag, 256, ATT_SMEM>>>();

    // Wo projection
    tc_gemm16<0><<<gv, 256, GEMM16_SMEM>>>(pc16, pw16 + DD * DD, out);
}

// round 15
// speedup vs baseline: 1.5333x; 1.5333x over previous
#include <cuda_runtime.h>
#include <cuda_bf16.h>
#include <cuda_fp16.h>
#include <math.h>
#include <stdint.h>

#define BB   8
#define SS   1024
#define DD   1024
#define HH   16
#define DK   64

__device__ __forceinline__ uint32_t smem_u32(const void* p) {
    uint32_t a;
    asm("{ .reg .u64 t; cvta.to.shared.u64 t, %1; cvt.u32.u64 %0, t; }"
        : "=r"(a) : "l"(p));
    return a;
}

#define CP_ASYNC16(dst, src) \
    asm volatile("cp.async.cg.shared.global [%0], [%1], 16;" :: "r"(dst), "l"(src))
#define CP_COMMIT() asm volatile("cp.async.commit_group;" ::: "memory")
#define CP_WAIT0()  asm volatile("cp.async.wait_group 0;" ::: "memory")
#define CP_WAIT1()  asm volatile("cp.async.wait_group 1;" ::: "memory")

#define LDSM4(r, a)                                                          \
    asm volatile("ldmatrix.sync.aligned.m8n8.x4.shared.b16 {%0,%1,%2,%3}, [%4];" \
        : "=r"((r)[0]), "=r"((r)[1]), "=r"((r)[2]), "=r"((r)[3]) : "r"(a))
#define LDSM4T(r, a)                                                         \
    asm volatile("ldmatrix.sync.aligned.m8n8.x4.trans.shared.b16 {%0,%1,%2,%3}, [%4];" \
        : "=r"((r)[0]), "=r"((r)[1]), "=r"((r)[2]), "=r"((r)[3]) : "r"(a))

#define MMA_BF16(c, a, b)                                                    \
    asm volatile("mma.sync.aligned.m16n8k16.row.col.f32.bf16.bf16.f32 "      \
        "{%0,%1,%2,%3}, {%4,%5,%6,%7}, {%8,%9}, {%0,%1,%2,%3};"              \
        : "+f"((c)[0]), "+f"((c)[1]), "+f"((c)[2]), "+f"((c)[3])             \
        : "r"((a)[0]), "r"((a)[1]), "r"((a)[2]), "r"((a)[3]),                \
          "r"((b)[0]), "r"((b)[1]))
#define MMA_F16(c, a, b)                                                     \
    asm volatile("mma.sync.aligned.m16n8k16.row.col.f32.f16.f16.f32 "        \
        "{%0,%1,%2,%3}, {%4,%5,%6,%7}, {%8,%9}, {%0,%1,%2,%3};"              \
        : "+f"((c)[0]), "+f"((c)[1]), "+f"((c)[2]), "+f"((c)[3])             \
        : "r"((a)[0]), "r"((a)[1]), "r"((a)[2]), "r"((a)[3]),                \
          "r"((b)[0]), "r"((b)[1]))

__device__ __forceinline__ uint32_t packh2(float a, float b) {
    __half2 h = __floats2half2_rn(a, b);
    return *(uint32_t*)&h;
}
__device__ __forceinline__ uint32_t packbf2(float a, float b) {
    __nv_bfloat16 x = __float2bfloat16(a), y = __float2bfloat16(b);
    return (uint32_t)*(unsigned short*)&x | ((uint32_t)*(unsigned short*)&y << 16);
}

// ---------------------------------------------------------------------------
// Global scratch
// ---------------------------------------------------------------------------
__device__ float g_bias[HH * (2 * SS - 1)];
__device__ __nv_bfloat16 g_ahi[BB * SS * DD];
__device__ __nv_bfloat16 g_alo[BB * SS * DD];
__device__ __half        g_x16[BB * SS * DD];
__device__ __half        g_ctx16[BB * SS * DD];
__device__ __nv_bfloat16 g_wthi[2 * DD * DD];
__device__ __nv_bfloat16 g_wtlo[2 * DD * DD];
__device__ __half        g_w16[2 * DD * DD];
__device__ __nv_bfloat16 g_qhi[BB * HH * SS * DK];
__device__ __nv_bfloat16 g_qlo[BB * HH * SS * DK];
__device__ __nv_bfloat16 g_khi[BB * HH * SS * DK];
__device__ __nv_bfloat16 g_klo[BB * HH * SS * DK];
__device__ __half        g_vh [BB * HH * SS * DK];

// ---------------------------------------------------------------------------
// Bias table
// ---------------------------------------------------------------------------
__global__ void bias_kernel(const float* __restrict__ rel_emb) {
    int idx = blockIdx.x * blockDim.x + threadIdx.x;
    const int TAB = 2 * SS - 1;
    if (idx >= HH * TAB) return;
    int h = idx / TAB, pos = idx % TAB;
    int n = -(pos - (SS - 1));
    int ret = 0;
    if (n < 0) { ret = 16; n = -n; }
    int v;
    if (n < 8) v = n;
    else {
        int j = (31 - __clz(n * n)) - 6;
        v = 8 + j;
        if (v > 15) v = 15;
    }
    g_bias[idx] = rel_emb[(ret + v) * HH + h];
}

// ---------------------------------------------------------------------------
// fp32 -> bf16 hi/lo + fp16 (x)
// ---------------------------------------------------------------------------
__global__ void split_kernel(const float* __restrict__ src,
                             __nv_bfloat16* __restrict__ hi,
                             __nv_bfloat16* __restrict__ lo,
                             __half* __restrict__ h16, int n4) {
    int i = blockIdx.x * blockDim.x + threadIdx.x;
    if (i >= n4) return;
    float4 v = ((const float4*)src)[i];
    __nv_bfloat16 h[4], l[4];
    __half f[4];
    float vv[4] = {v.x, v.y, v.z, v.w};
#pragma unroll
    for (int j = 0; j < 4; ++j) {
        h[j] = __float2bfloat16(vv[j]);
        l[j] = __float2bfloat16(vv[j] - __bfloat162float(h[j]));
        f[j] = __float2half_rn(vv[j]);
    }
    *(uint2*)&hi[4 * i] = *(uint2*)h;
    *(uint2*)&lo[4 * i] = *(uint2*)l;
    *(uint2*)&h16[4 * i] = *(uint2*)f;
}

// ---------------------------------------------------------------------------
// Fused transpose+split of all 4 weights
// ---------------------------------------------------------------------------
__global__ void splitT4_kernel(const float* __restrict__ W0,
                               const float* __restrict__ W1,
                               const float* __restrict__ W2,
                               const float* __restrict__ W3,
                               __nv_bfloat16* __restrict__ hi,
                               __nv_bfloat16* __restrict__ lo,
                               __half* __restrict__ w16) {
    __shared__ float t[32][33];
    const int tx = threadIdx.x, ty = threadIdx.y;
    const int bx = blockIdx.x, by = blockIdx.y, bz = blockIdx.z;
    const float* W = (bz == 0) ? W0 : (bz == 1) ? W1 : (bz == 2) ? W2 : W3;
#pragma unroll
    for (int j = 0; j < 32; j += 8)
        t[ty + j][tx] = W[(by * 32 + ty + j) * DD + bx * 32 + tx];
    __syncthreads();
#pragma unroll
    for (int j = 0; j < 32; j += 8) {
        float v = t[tx][ty + j];
        size_t row = (size_t)(bx * 32 + ty + j) * DD + by * 32 + tx;
        if (bz < 2) {
            size_t o = (size_t)bz * DD * DD + row;
            __nv_bfloat16 h = __float2bfloat16(v);
            hi[o] = h;
            lo[o] = __float2bfloat16(v - __bfloat162float(h));
        } else {
            w16[(size_t)(bz - 2) * DD * DD + row] = __float2half_rn(v);
        }
    }
}

// ---------------------------------------------------------------------------
// Fused Q+K GEMM (N=2048), bf16 3-product split — R10/R11 proven mainloop.
// ---------------------------------------------------------------------------
#define T_B    8192
#define STG_B  (4 * T_B)
#define GEMM_SMEM (3 * STG_B)

__global__ __launch_bounds__(256, 2)
void tc_gemm_qk(const __nv_bfloat16* __restrict__ Ahi,
                const __nv_bfloat16* __restrict__ Alo,
                const __nv_bfloat16* __restrict__ Bhi,
                const __nv_bfloat16* __restrict__ Blo,
                void* __restrict__ oQh, void* __restrict__ oQl,
                void* __restrict__ oKh, void* __restrict__ oKl) {
    extern __shared__ __align__(128) char smc[];
    const uint32_t sb = smem_u32(smc);
    const int tid = threadIdx.x;
    const int lane = tid & 31, wid = tid >> 5;
    const int m0 = blockIdx.y * 128, n0 = blockIdx.x * 128;

    const int wm = (wid & 3) * 32;
    const int wn = (wid >> 2) * 64;

    const int arow = wm + (lane & 15);
    const uint32_t abase = (uint32_t)arow * 64;
    const int aswz = (arow >> 1) & 3;
    const int ahb = lane >> 4;
    const int brow = wn + (lane & 7) + (lane >> 4) * 8;
    const uint32_t bbase = (uint32_t)brow * 64;
    const int bswz = (brow >> 1) & 3;
    const int bhb = (lane >> 3) & 1;

    float c[2][8][4];
#pragma unroll
    for (int i = 0; i < 2; ++i)
#pragma unroll
        for (int j = 0; j < 8; ++j)
#pragma unroll
            for (int q = 0; q < 4; ++q) c[i][j][q] = 0.0f;

    const int NIT = 32;

    auto issue = [&](int t) {
        const int kb = t * 32;
        const uint32_t stg = sb + (t % 3) * STG_B;
        const char* s0 = (const char*)(Ahi + (size_t)m0 * DD + kb);
        const char* s1 = (const char*)(Alo + (size_t)m0 * DD + kb);
        const char* s2 = (const char*)(Bhi + (size_t)n0 * DD + kb);
        const char* s3 = (const char*)(Blo + (size_t)n0 * DD + kb);
#pragma unroll
        for (int j = 0; j < 8; ++j) {
            const int idx = tid + j * 256;
            const int tile = idx >> 9, rem = idx & 511;
            const int row = rem >> 2, ch = rem & 3;
            const int phys = ch ^ ((row >> 1) & 3);
            const char* src =
                ((tile == 0) ? s0 : (tile == 1) ? s1 : (tile == 2) ? s2 : s3) +
                (size_t)row * 2048 + ch * 16;
            CP_ASYNC16(stg + tile * T_B + row * 64 + phys * 16, src);
        }
    };

    issue(0); CP_COMMIT();
    issue(1); CP_COMMIT();

    for (int t = 0; t < NIT; ++t) {
        CP_WAIT1();
        __syncthreads();
        if (t + 2 < NIT) issue(t + 2);
        CP_COMMIT();

        const uint32_t stg = sb + (t % 3) * STG_B;
#pragma unroll
        for (int s = 0; s < 2; ++s) {
            const uint32_t ac = (uint32_t)(((s * 2 + ahb) ^ aswz) * 16);
            const uint32_t bc = (uint32_t)(((s * 2 + bhb) ^ bswz) * 16);
            uint32_t ah[2][4], al[2][4], bf[4][4];
#pragma unroll
            for (int mi = 0; mi < 2; ++mi) {
                LDSM4(ah[mi], stg + abase + mi * 1024 + ac);
                LDSM4(al[mi], stg + T_B + abase + mi * 1024 + ac);
            }
#pragma unroll
            for (int p = 0; p < 4; ++p)
                LDSM4(bf[p], stg + 2 * T_B + bbase + p * 1024 + bc);
#pragma unroll
            for (int mi = 0; mi < 2; ++mi)
#pragma unroll
                for (int nj = 0; nj < 8; ++nj) {
                    uint32_t b2[2] = {bf[nj >> 1][(nj & 1) * 2],
                                      bf[nj >> 1][(nj & 1) * 2 + 1]};
                    MMA_BF16(c[mi][nj], ah[mi], b2);
                    MMA_BF16(c[mi][nj], al[mi], b2);
                }
#pragma unroll
            for (int p = 0; p < 4; ++p)
                LDSM4(bf[p], stg + 3 * T_B + bbase + p * 1024 + bc);
#pragma unroll
            for (int mi = 0; mi < 2; ++mi)
#pragma unroll
                for (int nj = 0; nj < 8; ++nj) {
                    uint32_t b2[2] = {bf[nj >> 1][(nj & 1) * 2],
                                      bf[nj >> 1][(nj & 1) * 2 + 1]};
                    MMA_BF16(c[mi][nj], ah[mi], b2);
                }
        }
    }

    const int sect = n0 >> 10;
    void* oh = (sect == 0) ? oQh : oKh;
    void* ol = (sect == 0) ? oQl : oKl;
#pragma unroll
    for (int mi = 0; mi < 2; ++mi) {
#pragma unroll
        for (int nj = 0; nj < 8; ++nj) {
            const int col = n0 + wn + nj * 8 + (lane & 3) * 2;
            const int r = m0 + wm + mi * 16 + (lane >> 2);
            const int cw = col & 1023;
            const int h = cw >> 6, d = cw & 63;
#pragma unroll
            for (int half = 0; half < 2; ++half) {
                const int rr = r + half * 8;
                const int b = rr >> 10, s2 = rr & 1023;
                const size_t idx = ((size_t)((b << 4) + h) * 1024 + s2) * 64 + d;
                float v0 = c[mi][nj][half * 2], v1 = c[mi][nj][half * 2 + 1];
                __nv_bfloat16 h0 = __float2bfloat16(v0);
                __nv_bfloat16 h1 = __float2bfloat16(v1);
                ((uint32_t*)oh)[idx >> 1] =
                    (uint32_t)*(unsigned short*)&h0 |
                    ((uint32_t)*(unsigned short*)&h1 << 16);
                ((uint32_t*)ol)[idx >> 1] = packbf2(
                    v0 - __bfloat162float(h0), v1 - __bfloat162float(h1));
            }
        }
    }
}

// ---------------------------------------------------------------------------
// fp16 single-product GEMM, k64 stages (R11 proven version).
//   MODE 0: fp32 row-major out (Wo).  MODE 1: fp16 scatter [B,H,S,DK] (V).
// ---------------------------------------------------------------------------
#define T16_B  16384
#define STG16  (2 * T16_B)
#define GEMM16_SMEM (3 * STG16)

template <int MODE>
__global__ __launch_bounds__(256, 2)
void tc_gemm16(const __half* __restrict__ A,
               const __half* __restrict__ Bm,
               void* __restrict__ out) {
    extern __shared__ __align__(128) char smc[];
    const uint32_t sb = smem_u32(smc);
    const int tid = threadIdx.x;
    const int lane = tid & 31, wid = tid >> 5;
    const int m0 = blockIdx.y * 128, n0 = blockIdx.x * 128;

    const int wm = (wid & 3) * 32;
    const int wn = (wid >> 2) * 64;
    const int arow = wm + (lane & 15);
    const uint32_t abase = (uint32_t)arow * 128;
    const int asw = arow & 7;
    const int ahb = lane >> 4;
    const int brow = wn + (lane & 7) + (lane >> 4) * 8;
    const uint32_t bbase = (uint32_t)brow * 128;
    const int bsw = brow & 7;
    const int bhb = (lane >> 3) & 1;

    float c[2][8][4];
#pragma unroll
    for (int i = 0; i < 2; ++i)
#pragma unroll
        for (int j = 0; j < 8; ++j)
#pragma unroll
            for (int q = 0; q < 4; ++q) c[i][j][q] = 0.0f;

    const int NIT = 16;   // k64 chunks

    auto issue = [&](int t) {
        const int kbB = t * 128;       // byte offset of k-chunk (64 fp16)
        const uint32_t stg = sb + (t % 3) * STG16;
        const char* s0 = (const char*)(A + (size_t)m0 * DD) + kbB;
        const char* s1 = (const char*)(Bm + (size_t)n0 * DD) + kbB;
#pragma unroll
        for (int j = 0; j < 8; ++j) {
            const int idx = tid + j * 256;        // 2048 = 2 tiles x 1024
            const int tile = idx >> 10, rem = idx & 1023;
            const int row = rem >> 3, ch = rem & 7;
            const int phys = ch ^ (row & 7);
            const char* src = (tile ? s1 : s0) + (size_t)row * 2048 + ch * 16;
            CP_ASYNC16(stg + tile * T16_B + row * 128 + phys * 16, src);
        }
    };

    issue(0); CP_COMMIT();
    issue(1); CP_COMMIT();

    for (int t = 0; t < NIT; ++t) {
        CP_WAIT1();
        __syncthreads();
        if (t + 2 < NIT) issue(t + 2);
        CP_COMMIT();

        const uint32_t stg = sb + (t % 3) * STG16;
#pragma unroll
        for (int s = 0; s < 4; ++s) {             // 4 k16 phases per k64
            const uint32_t ac = (uint32_t)(((s * 2 + ahb) ^ asw) * 16);
            const uint32_t bc = (uint32_t)(((s * 2 + bhb) ^ bsw) * 16);
            uint32_t ah[2][4], bf[4][4];
#pragma unroll
            for (int mi = 0; mi < 2; ++mi)
                LDSM4(ah[mi], stg + abase + mi * (16 * 128) + ac);
#pragma unroll
            for (int p = 0; p < 4; ++p)
                LDSM4(bf[p], stg + T16_B + bbase + p * (16 * 128) + bc);
#pragma unroll
            for (int mi = 0; mi < 2; ++mi)
#pragma unroll
                for (int nj = 0; nj < 8; ++nj) {
                    uint32_t b2[2] = {bf[nj >> 1][(nj & 1) * 2],
                                      bf[nj >> 1][(nj & 1) * 2 + 1]};
                    MMA_F16(c[mi][nj], ah[mi], b2);
                }
        }
    }

#pragma unroll
    for (int mi = 0; mi < 2; ++mi) {
#pragma unroll
        for (int nj = 0; nj < 8; ++nj) {
            const int col = n0 + wn + nj * 8 + (lane & 3) * 2;
            const int r = m0 + wm + mi * 16 + (lane >> 2);
            if (MODE == 0) {
                float* o = (float*)out;
                *(float2*)&o[(size_t)r * DD + col] =
                    make_float2(c[mi][nj][0], c[mi][nj][1]);
                *(float2*)&o[(size_t)(r + 8) * DD + col] =
                    make_float2(c[mi][nj][2], c[mi][nj][3]);
            } else {
                const int h = col >> 6, d = col & 63;
#pragma unroll
                for (int half = 0; half < 2; ++half) {
                    const int rr = r + half * 8;
                    const int b = rr >> 10, s2 = rr & 1023;
                    const size_t idx =
                        ((size_t)((b << 4) + h) * 1024 + s2) * 64 + d;
                    ((uint32_t*)out)[idx >> 1] =
                        packh2(c[mi][nj][half * 2], c[mi][nj][half * 2 + 1]);
                }
            }
        }
    }
}

// ---------------------------------------------------------------------------
// Tensor-core flash attention — UNCHANGED (proven).
// ---------------------------------------------------------------------------
#define KT      64
#define RSB     144
#define Q_B     (128 * RSB)
#define KV_T    (KT * RSB)
#define KV_STG  (3 * KV_T)
#define SM_KV   (2 * Q_B)
#define SM_BIAS (SM_KV + 2 * KV_STG)
#define ATT_SMEM (SM_BIAS + 1152 * 4)

__global__ __launch_bounds__(256, 2)
void attn_kernel() {
    extern __shared__ __align__(128) char smc[];
    const uint32_t sb = smem_u32(smc);
    float* bs = (float*)(smc + SM_BIAS);

    const int tid = threadIdx.x;
    const int lane = tid & 31, wid = tid >> 5;
    const int q0 = blockIdx.x * 128;
    const int h = blockIdx.y, b = blockIdx.z;
    const size_t hd = (size_t)(b * HH + h) * SS * DK;

    const int wm = wid * 16;
    const uint32_t aoff = (uint32_t)(wm + (lane & 15)) * RSB + (lane >> 4) * 16;
    const uint32_t boff = (uint32_t)((lane & 7) + (lane >> 4) * 8) * RSB +
                          ((lane >> 3) & 1) * 16;
    const uint32_t voff = (uint32_t)(lane & 15) * RSB + (lane >> 4) * 16;

    {
        const char* qh = (const char*)(g_qhi + hd + (size_t)q0 * DK);
        const char* ql = (const char*)(g_qlo + hd + (size_t)q0 * DK);
#pragma unroll
        for (int j = 0; j < 4; ++j) {
            int idx = tid + j * 256;
            int row = idx >> 3, ch = (idx & 7) * 16;
            CP_ASYNC16(sb + row * RSB + ch, qh + row * 128 + ch);
            CP_ASYNC16(sb + Q_B + row * RSB + ch, ql + row * 128 + ch);
        }
        for (int i = tid; i < 1151; i += 256)
            bs[i] = g_bias[h * (2 * SS - 1) + (896 - q0) + i];
    }
    auto issue_kv = [&](int kt) {
        const uint32_t stg = sb + SM_KV + (kt & 1) * KV_STG;
        const int k0 = kt * KT;
        const char* kh = (const char*)(g_khi + hd + (size_t)k0 * DK);
        const char* kl = (const char*)(g_klo + hd + (size_t)k0 * DK);
        const char* vv = (const char*)(g_vh + hd + (size_t)k0 * DK);
#pragma unroll
        for (int j = 0; j < 6; ++j) {
            int idx = tid + j * 256;
            int tile = idx >> 9, rem = idx & 511;
            int row = rem >> 3, ch = (rem & 7) * 16;
            const char* src = (tile == 0 ? kh : (tile == 1 ? kl : vv));
            CP_ASYNC16(stg + tile * KV_T + row * RSB + ch, src + row * 128 + ch);
        }
    };
    issue_kv(0);
    CP_COMMIT();

    float o[8][4];
#pragma unroll
    for (int j = 0; j < 8; ++j)
#pragma unroll
        for (int e = 0; e < 4; ++e) o[j][e] = 0.0f;
    float m0r = -1e30f, m1r = -1e30f, l0 = 0.0f, l1 = 0.0f;

    for (int kt = 0; kt < SS / KT; ++kt) {
        CP_WAIT0();
        __syncthreads();
        if (kt + 1 < SS / KT) { issue_kv(kt + 1); CP_COMMIT(); }

        const uint32_t kbh = sb + SM_KV + (kt & 1) * KV_STG;
        const uint32_t kbl = kbh + KV_T;
        const uint32_t vbb = kbh + 2 * KV_T;
        const int k0 = kt * KT;

        float s[8][4];
#pragma unroll
        for (int j = 0; j < 8; ++j)
#pragma unroll
            for (int e = 0; e < 4; ++e) s[j][e] = 0.0f;

#pragma unroll
        for (int ks = 0; ks < 4; ++ks) {
            uint32_t ah[4], al[4];
            LDSM4(ah, sb + aoff + ks * 32);
            LDSM4(al, sb + Q_B + aoff + ks * 32);
#pragma unroll
            for (int p = 0; p < 4; ++p) {
                uint32_t bh[4], bl[4];
                LDSM4(bh, kbh + boff + p * (16 * RSB) + ks * 32);
                LDSM4(bl, kbl + boff + p * (16 * RSB) + ks * 32);
                MMA_BF16(s[2 * p], ah, bh);
                MMA_BF16(s[2 * p + 1], ah, bh + 2);
                MMA_BF16(s[2 * p], al, bh);
                MMA_BF16(s[2 * p + 1], al, bh + 2);
                MMA_BF16(s[2 * p], ah, bl);
                MMA_BF16(s[2 * p + 1], ah, bl + 2);
            }
        }

        const int qr0 = wm + (lane >> 2);
        const int cb0 = 127 + k0 + (lane & 3) * 2;
#pragma unroll
        for (int nj = 0; nj < 8; ++nj) {
            const int t0 = cb0 + nj * 8;
            s[nj][0] += bs[t0 - qr0];
            s[nj][1] += bs[t0 + 1 - qr0];
            s[nj][2] += bs[t0 - qr0 - 8];
            s[nj][3] += bs[t0 + 1 - qr0 - 8];
        }
        float mx0 = -1e30f, mx1 = -1e30f;
#pragma unroll
        for (int nj = 0; nj < 8; ++nj) {
            mx0 = fmaxf(mx0, fmaxf(s[nj][0], s[nj][1]));
            mx1 = fmaxf(mx1, fmaxf(s[nj][2], s[nj][3]));
        }
        mx0 = fmaxf(mx0, __shfl_xor_sync(0xffffffffu, mx0, 1));
        mx0 = fmaxf(mx0, __shfl_xor_sync(0xffffffffu, mx0, 2));
        mx1 = fmaxf(mx1, __shfl_xor_sync(0xffffffffu, mx1, 1));
        mx1 = fmaxf(mx1, __shfl_xor_sync(0xffffffffu, mx1, 2));
        const float mn0 = fmaxf(m0r, mx0), mn1 = fmaxf(m1r, mx1);
        const float al0 = __expf(m0r - mn0), al1 = __expf(m1r - mn1);
        m0r = mn0; m1r = mn1;
        float sum0 = 0.0f, sum1 = 0.0f;
#pragma unroll
        for (int nj = 0; nj < 8; ++nj) {
            s[nj][0] = __expf(s[nj][0] - mn0);
            s[nj][1] = __expf(s[nj][1] - mn0);
            s[nj][2] = __expf(s[nj][2] - mn1);
            s[nj][3] = __expf(s[nj][3] - mn1);
            sum0 += s[nj][0] + s[nj][1];
            sum1 += s[nj][2] + s[nj][3];
            o[nj][0] *= al0; o[nj][1] *= al0;
            o[nj][2] *= al1; o[nj][3] *= al1;
        }
        sum0 += __shfl_xor_sync(0xffffffffu, sum0, 1);
        sum0 += __shfl_xor_sync(0xffffffffu, sum0, 2);
        sum1 += __shfl_xor_sync(0xffffffffu, sum1, 1);
        sum1 += __shfl_xor_sync(0xffffffffu, sum1, 2);
        l0 = l0 * al0 + sum0;
        l1 = l1 * al1 + sum1;

#pragma unroll
        for (int kc = 0; kc < 4; ++kc) {
            uint32_t ap[4];
            ap[0] = packh2(s[2 * kc][0], s[2 * kc][1]);
            ap[1] = packh2(s[2 * kc][2], s[2 * kc][3]);
            ap[2] = packh2(s[2 * kc + 1][0], s[2 * kc + 1][1]);
            ap[3] = packh2(s[2 * kc + 1][2], s[2 * kc + 1][3]);
#pragma unroll
            for (int nb = 0; nb < 4; ++nb) {
                uint32_t bt[4];
                LDSM4T(bt, vbb + voff + kc * (16 * RSB) + nb * 32);
                MMA_F16(o[2 * nb], ap, bt);
                MMA_F16(o[2 * nb + 1], ap, bt + 2);
            }
        }
    }

    const float inv0 = 1.0f / l0, inv1 = 1.0f / l1;
    const int row0 = q0 + wm + (lane >> 2);
    const size_t base0 = ((size_t)(b * SS) + row0) * DD + h * 64;
    const size_t base1 = base0 + 8 * DD;
#pragma unroll
    for (int nj = 0; nj < 8; ++nj) {
        const int d = nj * 8 + (lane & 3) * 2;
        ((uint32_t*)g_ctx16)[(base0 + d) >> 1] =
            packh2(o[nj][0] * inv0, o[nj][1] * inv0);
        ((uint32_t*)g_ctx16)[(base1 + d) >> 1] =
            packh2(o[nj][2] * inv1, o[nj][3] * inv1);
    }
}

// ---------------------------------------------------------------------------
// Launch — R11 topology (proven best).
// ---------------------------------------------------------------------------
extern "C" void kernel_launch(void* const* d_in, const int* in_sizes, int n_in,
                              void* d_out, int out_size) {
    const float* x   = (const float*)d_in[0];
    const float* Wq  = (const float*)d_in[1];
    const float* Wk  = (const float*)d_in[2];
    const float* Wv  = (const float*)d_in[3];
    const float* Wo  = (const float*)d_in[4];
    const float* rel = (const float*)d_in[5];
    float* out = (float*)d_out;

    __nv_bfloat16 *pah, *pal, *pwh, *pwl, *pqh, *pql, *pkh, *pkl;
    __half *pvh, *px16, *pc16, *pw16;
    cudaGetSymbolAddress((void**)&pah, g_ahi);
    cudaGetSymbolAddress((void**)&pal, g_alo);
    cudaGetSymbolAddress((void**)&px16, g_x16);
    cudaGetSymbolAddress((void**)&pc16, g_ctx16);
    cudaGetSymbolAddress((void**)&pwh, g_wthi);
    cudaGetSymbolAddress((void**)&pwl, g_wtlo);
    cudaGetSymbolAddress((void**)&pw16, g_w16);
    cudaGetSymbolAddress((void**)&pqh, g_qhi);
    cudaGetSymbolAddress((void**)&pql, g_qlo);
    cudaGetSymbolAddress((void**)&pkh, g_khi);
    cudaGetSymbolAddress((void**)&pkl, g_klo);
    cudaGetSymbolAddress((void**)&pvh, g_vh);

    static cudaStream_t sv = nullptr;
    static cudaEvent_t ev0 = nullptr, ev1 = nullptr, ev2 = nullptr, ev3 = nullptr;
    if (!sv) {
        cudaStreamCreateWithFlags(&sv, cudaStreamNonBlocking);
        cudaEventCreateWithFlags(&ev0, cudaEventDisableTiming);
        cudaEventCreateWithFlags(&ev1, cudaEventDisableTiming);
        cudaEventCreateWithFlags(&ev2, cudaEventDisableTiming);
        cudaEventCreateWithFlags(&ev3, cudaEventDisableTiming);
        cudaFuncSetAttribute(tc_gemm_qk, cudaFuncAttributeMaxDynamicSharedMemorySize, GEMM_SMEM);
        cudaFuncSetAttribute(tc_gemm16<0>, cudaFuncAttributeMaxDynamicSharedMemorySize, GEMM16_SMEM);
        cudaFuncSetAttribute(tc_gemm16<1>, cudaFuncAttributeMaxDynamicSharedMemorySize, GEMM16_SMEM);
        cudaFuncSetAttribute(attn_kernel, cudaFuncAttributeMaxDynamicSharedMemorySize, ATT_SMEM);
    }

    // fork: side stream does weights transpose/split + bias table
    cudaEventRecord(ev0, 0);
    cudaStreamWaitEvent(sv, ev0, 0);

    dim3 tg(32, 32, 4), tb(32, 8);
    splitT4_kernel<<<tg, tb, 0, sv>>>(Wq, Wk, Wv, Wo, pwh, pwl, pw16);
    bias_kernel<<<(HH * (2 * SS - 1) + 255) / 256, 256, 0, sv>>>(rel);

    const int n4 = BB * SS * DD / 4;
    split_kernel<<<(n4 + 255) / 256, 256>>>(x, pah, pal, px16, n4);

    // join: both split products ready
    cudaEventRecord(ev1, sv);
    cudaStreamWaitEvent(0, ev1, 0);

    // fork: V projection (side) concurrent with Q+K GEMM (main)
    cudaEventRecord(ev2, 0);
    cudaStreamWaitEvent(sv, ev2, 0);

    dim3 gv(DD / 128, (BB * SS) / 128);       // (8, 64)
    tc_gemm16<1><<<gv, 256, GEMM16_SMEM, sv>>>(px16, pw16, pvh);

    dim3 gqk(2 * DD / 128, (BB * SS) / 128);  // (16, 64)
    tc_gemm_qk<<<gqk, 256, GEMM_SMEM>>>(pah, pal, pwh, pwl,
                                        pqh, pql, pkh, pkl);

    // join before attention
    cudaEventRecord(ev3, sv);
    cudaStreamWaitEvent(0, ev3, 0);

    dim3 ag(SS / 128, HH, BB);
    attn_kernel<<<ag, 256, ATT_SMEM>>>();

    // Wo projection
    tc_gemm16<0><<<gv, 256, GEMM16_SMEM>>>(pc16, pw16 + DD * DD, out);
}

// round 16
// speedup vs baseline: 1.5551x; 1.0142x over previous
#include <cuda_runtime.h>
#include <cuda_bf16.h>
#include <cuda_fp16.h>
#include <math.h>
#include <stdint.h>

#define BB   8
#define SS   1024
#define DD   1024
#define HH   16
#define DK   64

__device__ __forceinline__ uint32_t smem_u32(const void* p) {
    uint32_t a;
    asm("{ .reg .u64 t; cvta.to.shared.u64 t, %1; cvt.u32.u64 %0, t; }"
        : "=r"(a) : "l"(p));
    return a;
}

#define CP_ASYNC16(dst, src) \
    asm volatile("cp.async.cg.shared.global [%0], [%1], 16;" :: "r"(dst), "l"(src))
#define CP_COMMIT() asm volatile("cp.async.commit_group;" ::: "memory")
#define CP_WAIT0()  asm volatile("cp.async.wait_group 0;" ::: "memory")
#define CP_WAIT1()  asm volatile("cp.async.wait_group 1;" ::: "memory")

#define LDSM4(r, a)                                                          \
    asm volatile("ldmatrix.sync.aligned.m8n8.x4.shared.b16 {%0,%1,%2,%3}, [%4];" \
        : "=r"((r)[0]), "=r"((r)[1]), "=r"((r)[2]), "=r"((r)[3]) : "r"(a))
#define LDSM4T(r, a)                                                         \
    asm volatile("ldmatrix.sync.aligned.m8n8.x4.trans.shared.b16 {%0,%1,%2,%3}, [%4];" \
        : "=r"((r)[0]), "=r"((r)[1]), "=r"((r)[2]), "=r"((r)[3]) : "r"(a))

#define MMA_BF16(c, a, b)                                                    \
    asm volatile("mma.sync.aligned.m16n8k16.row.col.f32.bf16.bf16.f32 "      \
        "{%0,%1,%2,%3}, {%4,%5,%6,%7}, {%8,%9}, {%0,%1,%2,%3};"              \
        : "+f"((c)[0]), "+f"((c)[1]), "+f"((c)[2]), "+f"((c)[3])             \
        : "r"((a)[0]), "r"((a)[1]), "r"((a)[2]), "r"((a)[3]),                \
          "r"((b)[0]), "r"((b)[1]))
#define MMA_F16(c, a, b)                                                     \
    asm volatile("mma.sync.aligned.m16n8k16.row.col.f32.f16.f16.f32 "        \
        "{%0,%1,%2,%3}, {%4,%5,%6,%7}, {%8,%9}, {%0,%1,%2,%3};"              \
        : "+f"((c)[0]), "+f"((c)[1]), "+f"((c)[2]), "+f"((c)[3])             \
        : "r"((a)[0]), "r"((a)[1]), "r"((a)[2]), "r"((a)[3]),                \
          "r"((b)[0]), "r"((b)[1]))

__device__ __forceinline__ uint32_t packh2(float a, float b) {
    __half2 h = __floats2half2_rn(a, b);
    return *(uint32_t*)&h;
}
__device__ __forceinline__ uint32_t packbf2(float a, float b) {
    __nv_bfloat16 x = __float2bfloat16(a), y = __float2bfloat16(b);
    return (uint32_t)*(unsigned short*)&x | ((uint32_t)*(unsigned short*)&y << 16);
}

// ---------------------------------------------------------------------------
// Global scratch
// ---------------------------------------------------------------------------
__device__ float g_bias[HH * (2 * SS - 1)];
__device__ __nv_bfloat16 g_ahi[BB * SS * DD];
__device__ __nv_bfloat16 g_alo[BB * SS * DD];
__device__ __half        g_x16[BB * SS * DD];
__device__ __half        g_ctx16[BB * SS * DD];
__device__ __nv_bfloat16 g_wthi[2 * DD * DD];
__device__ __nv_bfloat16 g_wtlo[2 * DD * DD];
__device__ __half        g_w16[2 * DD * DD];
__device__ __nv_bfloat16 g_qhi[BB * HH * SS * DK];
__device__ __nv_bfloat16 g_qlo[BB * HH * SS * DK];
__device__ __nv_bfloat16 g_khi[BB * HH * SS * DK];
__device__ __nv_bfloat16 g_klo[BB * HH * SS * DK];
__device__ __half        g_vh [BB * HH * SS * DK];

// ---------------------------------------------------------------------------
// Bias table
// ---------------------------------------------------------------------------
__global__ void bias_kernel(const float* __restrict__ rel_emb) {
    int idx = blockIdx.x * blockDim.x + threadIdx.x;
    const int TAB = 2 * SS - 1;
    if (idx >= HH * TAB) return;
    int h = idx / TAB, pos = idx % TAB;
    int n = -(pos - (SS - 1));
    int ret = 0;
    if (n < 0) { ret = 16; n = -n; }
    int v;
    if (n < 8) v = n;
    else {
        int j = (31 - __clz(n * n)) - 6;
        v = 8 + j;
        if (v > 15) v = 15;
    }
    g_bias[idx] = rel_emb[(ret + v) * HH + h];
}

// ---------------------------------------------------------------------------
// fp32 -> bf16 hi/lo + fp16 (x)
// ---------------------------------------------------------------------------
__global__ void split_kernel(const float* __restrict__ src,
                             __nv_bfloat16* __restrict__ hi,
                             __nv_bfloat16* __restrict__ lo,
                             __half* __restrict__ h16, int n4) {
    int i = blockIdx.x * blockDim.x + threadIdx.x;
    if (i >= n4) return;
    float4 v = ((const float4*)src)[i];
    __nv_bfloat16 h[4], l[4];
    __half f[4];
    float vv[4] = {v.x, v.y, v.z, v.w};
#pragma unroll
    for (int j = 0; j < 4; ++j) {
        h[j] = __float2bfloat16(vv[j]);
        l[j] = __float2bfloat16(vv[j] - __bfloat162float(h[j]));
        f[j] = __float2half_rn(vv[j]);
    }
    *(uint2*)&hi[4 * i] = *(uint2*)h;
    *(uint2*)&lo[4 * i] = *(uint2*)l;
    *(uint2*)&h16[4 * i] = *(uint2*)f;
}

// ---------------------------------------------------------------------------
// Fused transpose+split of all 4 weights
// ---------------------------------------------------------------------------
__global__ void splitT4_kernel(const float* __restrict__ W0,
                               const float* __restrict__ W1,
                               const float* __restrict__ W2,
                               const float* __restrict__ W3,
                               __nv_bfloat16* __restrict__ hi,
                               __nv_bfloat16* __restrict__ lo,
                               __half* __restrict__ w16) {
    __shared__ float t[32][33];
    const int tx = threadIdx.x, ty = threadIdx.y;
    const int bx = blockIdx.x, by = blockIdx.y, bz = blockIdx.z;
    const float* W = (bz == 0) ? W0 : (bz == 1) ? W1 : (bz == 2) ? W2 : W3;
#pragma unroll
    for (int j = 0; j < 32; j += 8)
        t[ty + j][tx] = W[(by * 32 + ty + j) * DD + bx * 32 + tx];
    __syncthreads();
#pragma unroll
    for (int j = 0; j < 32; j += 8) {
        float v = t[tx][ty + j];
        size_t row = (size_t)(bx * 32 + ty + j) * DD + by * 32 + tx;
        if (bz < 2) {
            size_t o = (size_t)bz * DD * DD + row;
            __nv_bfloat16 h = __float2bfloat16(v);
            hi[o] = h;
            lo[o] = __float2bfloat16(v - __bfloat162float(h));
        } else {
            w16[(size_t)(bz - 2) * DD * DD + row] = __float2half_rn(v);
        }
    }
}

// ---------------------------------------------------------------------------
// Fused Q+K GEMM (N=2048), bf16 3-product split — R10/R11 proven mainloop.
// ---------------------------------------------------------------------------
#define T_B    8192
#define STG_B  (4 * T_B)
#define GEMM_SMEM (3 * STG_B)

__global__ __launch_bounds__(256, 2)
void tc_gemm_qk(const __nv_bfloat16* __restrict__ Ahi,
                const __nv_bfloat16* __restrict__ Alo,
                const __nv_bfloat16* __restrict__ Bhi,
                const __nv_bfloat16* __restrict__ Blo,
                void* __restrict__ oQh, void* __restrict__ oQl,
                void* __restrict__ oKh, void* __restrict__ oKl) {
    extern __shared__ __align__(128) char smc[];
    const uint32_t sb = smem_u32(smc);
    const int tid = threadIdx.x;
    const int lane = tid & 31, wid = tid >> 5;
    const int m0 = blockIdx.y * 128, n0 = blockIdx.x * 128;

    const int wm = (wid & 3) * 32;
    const int wn = (wid >> 2) * 64;

    const int arow = wm + (lane & 15);
    const uint32_t abase = (uint32_t)arow * 64;
    const int aswz = (arow >> 1) & 3;
    const int ahb = lane >> 4;
    const int brow = wn + (lane & 7) + (lane >> 4) * 8;
    const uint32_t bbase = (uint32_t)brow * 64;
    const int bswz = (brow >> 1) & 3;
    const int bhb = (lane >> 3) & 1;

    float c[2][8][4];
#pragma unroll
    for (int i = 0; i < 2; ++i)
#pragma unroll
        for (int j = 0; j < 8; ++j)
#pragma unroll
            for (int q = 0; q < 4; ++q) c[i][j][q] = 0.0f;

    const int NIT = 32;

    auto issue = [&](int t) {
        const int kb = t * 32;
        const uint32_t stg = sb + (t % 3) * STG_B;
        const char* s0 = (const char*)(Ahi + (size_t)m0 * DD + kb);
        const char* s1 = (const char*)(Alo + (size_t)m0 * DD + kb);
        const char* s2 = (const char*)(Bhi + (size_t)n0 * DD + kb);
        const char* s3 = (const char*)(Blo + (size_t)n0 * DD + kb);
#pragma unroll
        for (int j = 0; j < 8; ++j) {
            const int idx = tid + j * 256;
            const int tile = idx >> 9, rem = idx & 511;
            const int row = rem >> 2, ch = rem & 3;
            const int phys = ch ^ ((row >> 1) & 3);
            const char* src =
                ((tile == 0) ? s0 : (tile == 1) ? s1 : (tile == 2) ? s2 : s3) +
                (size_t)row * 2048 + ch * 16;
            CP_ASYNC16(stg + tile * T_B + row * 64 + phys * 16, src);
        }
    };

    issue(0); CP_COMMIT();
    issue(1); CP_COMMIT();

    for (int t = 0; t < NIT; ++t) {
        CP_WAIT1();
        __syncthreads();
        if (t + 2 < NIT) issue(t + 2);
        CP_COMMIT();

        const uint32_t stg = sb + (t % 3) * STG_B;
#pragma unroll
        for (int s = 0; s < 2; ++s) {
            const uint32_t ac = (uint32_t)(((s * 2 + ahb) ^ aswz) * 16);
            const uint32_t bc = (uint32_t)(((s * 2 + bhb) ^ bswz) * 16);
            uint32_t ah[2][4], al[2][4], bf[4][4];
#pragma unroll
            for (int mi = 0; mi < 2; ++mi) {
                LDSM4(ah[mi], stg + abase + mi * 1024 + ac);
                LDSM4(al[mi], stg + T_B + abase + mi * 1024 + ac);
            }
#pragma unroll
            for (int p = 0; p < 4; ++p)
                LDSM4(bf[p], stg + 2 * T_B + bbase + p * 1024 + bc);
#pragma unroll
            for (int mi = 0; mi < 2; ++mi)
#pragma unroll
                for (int nj = 0; nj < 8; ++nj) {
                    uint32_t b2[2] = {bf[nj >> 1][(nj & 1) * 2],
                                      bf[nj >> 1][(nj & 1) * 2 + 1]};
                    MMA_BF16(c[mi][nj], ah[mi], b2);
                    MMA_BF16(c[mi][nj], al[mi], b2);
                }
#pragma unroll
            for (int p = 0; p < 4; ++p)
                LDSM4(bf[p], stg + 3 * T_B + bbase + p * 1024 + bc);
#pragma unroll
            for (int mi = 0; mi < 2; ++mi)
#pragma unroll
                for (int nj = 0; nj < 8; ++nj) {
                    uint32_t b2[2] = {bf[nj >> 1][(nj & 1) * 2],
                                      bf[nj >> 1][(nj & 1) * 2 + 1]};
                    MMA_BF16(c[mi][nj], ah[mi], b2);
                }
        }
    }

    const int sect = n0 >> 10;
    void* oh = (sect == 0) ? oQh : oKh;
    void* ol = (sect == 0) ? oQl : oKl;
#pragma unroll
    for (int mi = 0; mi < 2; ++mi) {
#pragma unroll
        for (int nj = 0; nj < 8; ++nj) {
            const int col = n0 + wn + nj * 8 + (lane & 3) * 2;
            const int r = m0 + wm + mi * 16 + (lane >> 2);
            const int cw = col & 1023;
            const int h = cw >> 6, d = cw & 63;
#pragma unroll
            for (int half = 0; half < 2; ++half) {
                const int rr = r + half * 8;
                const int b = rr >> 10, s2 = rr & 1023;
                const size_t idx = ((size_t)((b << 4) + h) * 1024 + s2) * 64 + d;
                float v0 = c[mi][nj][half * 2], v1 = c[mi][nj][half * 2 + 1];
                __nv_bfloat16 h0 = __float2bfloat16(v0);
                __nv_bfloat16 h1 = __float2bfloat16(v1);
                ((uint32_t*)oh)[idx >> 1] =
                    (uint32_t)*(unsigned short*)&h0 |
                    ((uint32_t)*(unsigned short*)&h1 << 16);
                ((uint32_t*)ol)[idx >> 1] = packbf2(
                    v0 - __bfloat162float(h0), v1 - __bfloat162float(h1));
            }
        }
    }
}

// ---------------------------------------------------------------------------
// fp16 single-product GEMM, k64 stages (R11 proven version).
//   MODE 0: fp32 row-major out (Wo).  MODE 1: fp16 scatter [B,H,S,DK] (V).
// ---------------------------------------------------------------------------
#define T16_B  16384
#define STG16  (2 * T16_B)
#define GEMM16_SMEM (3 * STG16)

template <int MODE>
__global__ __launch_bounds__(256, 2)
void tc_gemm16(const __half* __restrict__ A,
               const __half* __restrict__ Bm,
               void* __restrict__ out) {
    extern __shared__ __align__(128) char smc[];
    const uint32_t sb = smem_u32(smc);
    const int tid = threadIdx.x;
    const int lane = tid & 31, wid = tid >> 5;
    const int m0 = blockIdx.y * 128, n0 = blockIdx.x * 128;

    const int wm = (wid & 3) * 32;
    const int wn = (wid >> 2) * 64;
    const int arow = wm + (lane & 15);
    const uint32_t abase = (uint32_t)arow * 128;
    const int asw = arow & 7;
    const int ahb = lane >> 4;
    const int brow = wn + (lane & 7) + (lane >> 4) * 8;
    const uint32_t bbase = (uint32_t)brow * 128;
    const int bsw = brow & 7;
    const int bhb = (lane >> 3) & 1;

    float c[2][8][4];
#pragma unroll
    for (int i = 0; i < 2; ++i)
#pragma unroll
        for (int j = 0; j < 8; ++j)
#pragma unroll
            for (int q = 0; q < 4; ++q) c[i][j][q] = 0.0f;

    const int NIT = 16;

    auto issue = [&](int t) {
        const int kbB = t * 128;
        const uint32_t stg = sb + (t % 3) * STG16;
        const char* s0 = (const char*)(A + (size_t)m0 * DD) + kbB;
        const char* s1 = (const char*)(Bm + (size_t)n0 * DD) + kbB;
#pragma unroll
        for (int j = 0; j < 8; ++j) {
            const int idx = tid + j * 256;
            const int tile = idx >> 10, rem = idx & 1023;
            const int row = rem >> 3, ch = rem & 7;
            const int phys = ch ^ (row & 7);
            const char* src = (tile ? s1 : s0) + (size_t)row * 2048 + ch * 16;
            CP_ASYNC16(stg + tile * T16_B + row * 128 + phys * 16, src);
        }
    };

    issue(0); CP_COMMIT();
    issue(1); CP_COMMIT();

    for (int t = 0; t < NIT; ++t) {
        CP_WAIT1();
        __syncthreads();
        if (t + 2 < NIT) issue(t + 2);
        CP_COMMIT();

        const uint32_t stg = sb + (t % 3) * STG16;
#pragma unroll
        for (int s = 0; s < 4; ++s) {
            const uint32_t ac = (uint32_t)(((s * 2 + ahb) ^ asw) * 16);
            const uint32_t bc = (uint32_t)(((s * 2 + bhb) ^ bsw) * 16);
            uint32_t ah[2][4], bf[4][4];
#pragma unroll
            for (int mi = 0; mi < 2; ++mi)
                LDSM4(ah[mi], stg + abase + mi * (16 * 128) + ac);
#pragma unroll
            for (int p = 0; p < 4; ++p)
                LDSM4(bf[p], stg + T16_B + bbase + p * (16 * 128) + bc);
#pragma unroll
            for (int mi = 0; mi < 2; ++mi)
#pragma unroll
                for (int nj = 0; nj < 8; ++nj) {
                    uint32_t b2[2] = {bf[nj >> 1][(nj & 1) * 2],
                                      bf[nj >> 1][(nj & 1) * 2 + 1]};
                    MMA_F16(c[mi][nj], ah[mi], b2);
                }
        }
    }

#pragma unroll
    for (int mi = 0; mi < 2; ++mi) {
#pragma unroll
        for (int nj = 0; nj < 8; ++nj) {
            const int col = n0 + wn + nj * 8 + (lane & 3) * 2;
            const int r = m0 + wm + mi * 16 + (lane >> 2);
            if (MODE == 0) {
                float* o = (float*)out;
                *(float2*)&o[(size_t)r * DD + col] =
                    make_float2(c[mi][nj][0], c[mi][nj][1]);
                *(float2*)&o[(size_t)(r + 8) * DD + col] =
                    make_float2(c[mi][nj][2], c[mi][nj][3]);
            } else {
                const int h = col >> 6, d = col & 63;
#pragma unroll
                for (int half = 0; half < 2; ++half) {
                    const int rr = r + half * 8;
                    const int b = rr >> 10, s2 = rr & 1023;
                    const size_t idx =
                        ((size_t)((b << 4) + h) * 1024 + s2) * 64 + d;
                    ((uint32_t*)out)[idx >> 1] =
                        packh2(c[mi][nj][half * 2], c[mi][nj][half * 2 + 1]);
                }
            }
        }
    }
}

// ---------------------------------------------------------------------------
// Tensor-core flash attention — deferred row-sum reduction (per-thread
// partials, lane reduction once after the k-loop).
// ---------------------------------------------------------------------------
#define KT      64
#define RSB     144
#define Q_B     (128 * RSB)
#define KV_T    (KT * RSB)
#define KV_STG  (3 * KV_T)
#define SM_KV   (2 * Q_B)
#define SM_BIAS (SM_KV + 2 * KV_STG)
#define ATT_SMEM (SM_BIAS + 1152 * 4)

__global__ __launch_bounds__(256, 2)
void attn_kernel() {
    extern __shared__ __align__(128) char smc[];
    const uint32_t sb = smem_u32(smc);
    float* bs = (float*)(smc + SM_BIAS);

    const int tid = threadIdx.x;
    const int lane = tid & 31, wid = tid >> 5;
    const int q0 = blockIdx.x * 128;
    const int h = blockIdx.y, b = blockIdx.z;
    const size_t hd = (size_t)(b * HH + h) * SS * DK;

    const int wm = wid * 16;
    const uint32_t aoff = (uint32_t)(wm + (lane & 15)) * RSB + (lane >> 4) * 16;
    const uint32_t boff = (uint32_t)((lane & 7) + (lane >> 4) * 8) * RSB +
                          ((lane >> 3) & 1) * 16;
    const uint32_t voff = (uint32_t)(lane & 15) * RSB + (lane >> 4) * 16;

    {
        const char* qh = (const char*)(g_qhi + hd + (size_t)q0 * DK);
        const char* ql = (const char*)(g_qlo + hd + (size_t)q0 * DK);
#pragma unroll
        for (int j = 0; j < 4; ++j) {
            int idx = tid + j * 256;
            int row = idx >> 3, ch = (idx & 7) * 16;
            CP_ASYNC16(sb + row * RSB + ch, qh + row * 128 + ch);
            CP_ASYNC16(sb + Q_B + row * RSB + ch, ql + row * 128 + ch);
        }
        for (int i = tid; i < 1151; i += 256)
            bs[i] = g_bias[h * (2 * SS - 1) + (896 - q0) + i];
    }
    auto issue_kv = [&](int kt) {
        const uint32_t stg = sb + SM_KV + (kt & 1) * KV_STG;
        const int k0 = kt * KT;
        const char* kh = (const char*)(g_khi + hd + (size_t)k0 * DK);
        const char* kl = (const char*)(g_klo + hd + (size_t)k0 * DK);
        const char* vv = (const char*)(g_vh + hd + (size_t)k0 * DK);
#pragma unroll
        for (int j = 0; j < 6; ++j) {
            int idx = tid + j * 256;
            int tile = idx >> 9, rem = idx & 511;
            int row = rem >> 3, ch = (rem & 7) * 16;
            const char* src = (tile == 0 ? kh : (tile == 1 ? kl : vv));
            CP_ASYNC16(stg + tile * KV_T + row * RSB + ch, src + row * 128 + ch);
        }
    };
    issue_kv(0);
    CP_COMMIT();

    float o[8][4];
#pragma unroll
    for (int j = 0; j < 8; ++j)
#pragma unroll
        for (int e = 0; e < 4; ++e) o[j][e] = 0.0f;
    float m0r = -1e30f, m1r = -1e30f, l0 = 0.0f, l1 = 0.0f;

    for (int kt = 0; kt < SS / KT; ++kt) {
        CP_WAIT0();
        __syncthreads();
        if (kt + 1 < SS / KT) { issue_kv(kt + 1); CP_COMMIT(); }

        const uint32_t kbh = sb + SM_KV + (kt & 1) * KV_STG;
        const uint32_t kbl = kbh + KV_T;
        const uint32_t vbb = kbh + 2 * KV_T;
        const int k0 = kt * KT;

        float s[8][4];
#pragma unroll
        for (int j = 0; j < 8; ++j)
#pragma unroll
            for (int e = 0; e < 4; ++e) s[j][e] = 0.0f;

#pragma unroll
        for (int ks = 0; ks < 4; ++ks) {
            uint32_t ah[4], al[4];
            LDSM4(ah, sb + aoff + ks * 32);
            LDSM4(al, sb + Q_B + aoff + ks * 32);
#pragma unroll
            for (int p = 0; p < 4; ++p) {
                uint32_t bh[4], bl[4];
                LDSM4(bh, kbh + boff + p * (16 * RSB) + ks * 32);
                LDSM4(bl, kbl + boff + p * (16 * RSB) + ks * 32);
                MMA_BF16(s[2 * p], ah, bh);
                MMA_BF16(s[2 * p + 1], ah, bh + 2);
                MMA_BF16(s[2 * p], al, bh);
                MMA_BF16(s[2 * p + 1], al, bh + 2);
                MMA_BF16(s[2 * p], ah, bl);
                MMA_BF16(s[2 * p + 1], ah, bl + 2);
            }
        }

        const int qr0 = wm + (lane >> 2);
        const int cb0 = 127 + k0 + (lane & 3) * 2;
#pragma unroll
        for (int nj = 0; nj < 8; ++nj) {
            const int t0 = cb0 + nj * 8;
            s[nj][0] += bs[t0 - qr0];
            s[nj][1] += bs[t0 + 1 - qr0];
            s[nj][2] += bs[t0 - qr0 - 8];
            s[nj][3] += bs[t0 + 1 - qr0 - 8];
        }
        // per-tile max (must be exact; 2-shuffle reduction per row group)
        float mx0 = -1e30f, mx1 = -1e30f;
#pragma unroll
        for (int nj = 0; nj < 8; ++nj) {
            mx0 = fmaxf(mx0, fmaxf(s[nj][0], s[nj][1]));
            mx1 = fmaxf(mx1, fmaxf(s[nj][2], s[nj][3]));
        }
        mx0 = fmaxf(mx0, __shfl_xor_sync(0xffffffffu, mx0, 1));
        mx0 = fmaxf(mx0, __shfl_xor_sync(0xffffffffu, mx0, 2));
        mx1 = fmaxf(mx1, __shfl_xor_sync(0xffffffffu, mx1, 1));
        mx1 = fmaxf(mx1, __shfl_xor_sync(0xffffffffu, mx1, 2));
        const float mn0 = fmaxf(m0r, mx0), mn1 = fmaxf(m1r, mx1);
        const float al0 = __expf(m0r - mn0), al1 = __expf(m1r - mn1);
        m0r = mn0; m1r = mn1;
        // deferred sum: per-thread partials, NO shuffle here
        float sum0 = 0.0f, sum1 = 0.0f;
#pragma unroll
        for (int nj = 0; nj < 8; ++nj) {
            s[nj][0] = __expf(s[nj][0] - mn0);
            s[nj][1] = __expf(s[nj][1] - mn0);
            s[nj][2] = __expf(s[nj][2] - mn1);
            s[nj][3] = __expf(s[nj][3] - mn1);
            sum0 += s[nj][0] + s[nj][1];
            sum1 += s[nj][2] + s[nj][3];
            o[nj][0] *= al0; o[nj][1] *= al0;
            o[nj][2] *= al1; o[nj][3] *= al1;
        }
        l0 = l0 * al0 + sum0;
        l1 = l1 * al1 + sum1;

#pragma unroll
        for (int kc = 0; kc < 4; ++kc) {
            uint32_t ap[4];
            ap[0] = packh2(s[2 * kc][0], s[2 * kc][1]);
            ap[1] = packh2(s[2 * kc][2], s[2 * kc][3]);
            ap[2] = packh2(s[2 * kc + 1][0], s[2 * kc + 1][1]);
            ap[3] = packh2(s[2 * kc + 1][2], s[2 * kc + 1][3]);
#pragma unroll
            for (int nb = 0; nb < 4; ++nb) {
                uint32_t bt[4];
                LDSM4T(bt, vbb + voff + kc * (16 * RSB) + nb * 32);
                MMA_F16(o[2 * nb], ap, bt);
                MMA_F16(o[2 * nb + 1], ap, bt + 2);
            }
        }
    }

    // final lane reduction of the deferred sums (quad lanes share a row)
    l0 += __shfl_xor_sync(0xffffffffu, l0, 1);
    l0 += __shfl_xor_sync(0xffffffffu, l0, 2);
    l1 += __shfl_xor_sync(0xffffffffu, l1, 1);
    l1 += __shfl_xor_sync(0xffffffffu, l1, 2);

    const float inv0 = 1.0f / l0, inv1 = 1.0f / l1;
    const int row0 = q0 + wm + (lane >> 2);
    const size_t base0 = ((size_t)(b * SS) + row0) * DD + h * 64;
    const size_t base1 = base0 + 8 * DD;
#pragma unroll
    for (int nj = 0; nj < 8; ++nj) {
        const int d = nj * 8 + (lane & 3) * 2;
        ((uint32_t*)g_ctx16)[(base0 + d) >> 1] =
            packh2(o[nj][0] * inv0, o[nj][1] * inv0);
        ((uint32_t*)g_ctx16)[(base1 + d) >> 1] =
            packh2(o[nj][2] * inv1, o[nj][3] * inv1);
    }
}

// ---------------------------------------------------------------------------
// Launch — R11 topology (proven best).
// ---------------------------------------------------------------------------
extern "C" void kernel_launch(void* const* d_in, const int* in_sizes, int n_in,
                              void* d_out, int out_size) {
    const float* x   = (const float*)d_in[0];
    const float* Wq  = (const float*)d_in[1];
    const float* Wk  = (const float*)d_in[2];
    const float* Wv  = (const float*)d_in[3];
    const float* Wo  = (const float*)d_in[4];
    const float* rel = (const float*)d_in[5];
    float* out = (float*)d_out;

    __nv_bfloat16 *pah, *pal, *pwh, *pwl, *pqh, *pql, *pkh, *pkl;
    __half *pvh, *px16, *pc16, *pw16;
    cudaGetSymbolAddress((void**)&pah, g_ahi);
    cudaGetSymbolAddress((void**)&pal, g_alo);
    cudaGetSymbolAddress((void**)&px16, g_x16);
    cudaGetSymbolAddress((void**)&pc16, g_ctx16);
    cudaGetSymbolAddress((void**)&pwh, g_wthi);
    cudaGetSymbolAddress((void**)&pwl, g_wtlo);
    cudaGetSymbolAddress((void**)&pw16, g_w16);
    cudaGetSymbolAddress((void**)&pqh, g_qhi);
    cudaGetSymbolAddress((void**)&pql, g_qlo);
    cudaGetSymbolAddress((void**)&pkh, g_khi);
    cudaGetSymbolAddress((void**)&pkl, g_klo);
    cudaGetSymbolAddress((void**)&pvh, g_vh);

    static cudaStream_t sv = nullptr;
    static cudaEvent_t ev0 = nullptr, ev1 = nullptr, ev2 = nullptr, ev3 = nullptr;
    if (!sv) {
        cudaStreamCreateWithFlags(&sv, cudaStreamNonBlocking);
        cudaEventCreateWithFlags(&ev0, cudaEventDisableTiming);
        cudaEventCreateWithFlags(&ev1, cudaEventDisableTiming);
        cudaEventCreateWithFlags(&ev2, cudaEventDisableTiming);
        cudaEventCreateWithFlags(&ev3, cudaEventDisableTiming);
        cudaFuncSetAttribute(tc_gemm_qk, cudaFuncAttributeMaxDynamicSharedMemorySize, GEMM_SMEM);
        cudaFuncSetAttribute(tc_gemm16<0>, cudaFuncAttributeMaxDynamicSharedMemorySize, GEMM16_SMEM);
        cudaFuncSetAttribute(tc_gemm16<1>, cudaFuncAttributeMaxDynamicSharedMemorySize, GEMM16_SMEM);
        cudaFuncSetAttribute(attn_kernel, cudaFuncAttributeMaxDynamicSharedMemorySize, ATT_SMEM);
    }

    // fork: side stream does weights transpose/split + bias table
    cudaEventRecord(ev0, 0);
    cudaStreamWaitEvent(sv, ev0, 0);

    dim3 tg(32, 32, 4), tb(32, 8);
    splitT4_kernel<<<tg, tb, 0, sv>>>(Wq, Wk, Wv, Wo, pwh, pwl, pw16);
    bias_kernel<<<(HH * (2 * SS - 1) + 255) / 256, 256, 0, sv>>>(rel);

    const int n4 = BB * SS * DD / 4;
    split_kernel<<<(n4 + 255) / 256, 256>>>(x, pah, pal, px16, n4);

    // join: both split products ready
    cudaEventRecord(ev1, sv);
    cudaStreamWaitEvent(0, ev1, 0);

    // fork: V projection (side) concurrent with Q+K GEMM (main)
    cudaEventRecord(ev2, 0);
    cudaStreamWaitEvent(sv, ev2, 0);

    dim3 gv(DD / 128, (BB * SS) / 128);       // (8, 64)
    tc_gemm16<1><<<gv, 256, GEMM16_SMEM, sv>>>(px16, pw16, pvh);

    dim3 gqk(2 * DD / 128, (BB * SS) / 128);  // (16, 64)
    tc_gemm_qk<<<gqk, 256, GEMM_SMEM>>>(pah, pal, pwh, pwl,
                                        pqh, pql, pkh, pkl);

    // join before attention
    cudaEventRecord(ev3, sv);
    cudaStreamWaitEvent(0, ev3, 0);

    dim3 ag(SS / 128, HH, BB);
    attn_kernel<<<ag, 256, ATT_SMEM>>>();

    // Wo projection
    tc_gemm16<0><<<gv, 256, GEMM16_SMEM>>>(pc16, pw16 + DD * DD, out);
}